// round 6
// baseline (speedup 1.0000x reference)
#include <cuda_runtime.h>
#include <math.h>

#define SEQ   2048
#define DIM   4096
#define NH    32
#define NKV   8
#define HD    128
#define KVDIM (NKV*HD)   /* 1024 */

// ---------------- scratch (no allocations allowed) ----------------
__device__ float g_Q[SEQ*DIM];
__device__ float g_K[SEQ*KVDIM];
__device__ float g_V[SEQ*KVDIM];
__device__ float g_A[SEQ*DIM];

// =================================================================
// GEMM: C[M,N] = A[M,K] * B[N,K]^T   (both row-major, K contiguous)
// 128x128 tile, BK=8, 256 threads, 8x8 per thread (split 2x(4+4))
// =================================================================
#define GBM 128
#define GBN 128
#define GBK 8
#define GPAD 132   /* 132 % 32 == 4 and 132/4 == 33 (odd) -> conflict-free */

__global__ __launch_bounds__(256, 2)
void gemm_nt(const float* __restrict__ A, const float* __restrict__ B,
             float* __restrict__ C, int M, int N, int K)
{
    __shared__ float As[GBK][GPAD];
    __shared__ float Bs[GBK][GPAD];

    const int tid = threadIdx.x;
    const int tx  = tid & 15;
    const int ty  = tid >> 4;
    const int bm  = blockIdx.y * GBM;
    const int bn  = blockIdx.x * GBN;

    const int lr = tid >> 1;        // 0..127 (tile row loaded by this thread)
    const int lc = (tid & 1) * 4;   // 0 or 4 (k offset within BK)

    const float* Ag = A + (size_t)(bm + lr) * K + lc;
    const float* Bg = B + (size_t)(bn + lr) * K + lc;

    float acc[8][8];
#pragma unroll
    for (int i = 0; i < 8; i++)
#pragma unroll
        for (int j = 0; j < 8; j++) acc[i][j] = 0.f;

    float4 pa = *(const float4*)Ag;     // prefetch k0 = 0
    float4 pb = *(const float4*)Bg;

    for (int k0 = 0; k0 < K; k0 += GBK) {
        // stage current tile (conflict-free: addr%32 spans all banks)
        As[lc+0][lr] = pa.x; As[lc+1][lr] = pa.y;
        As[lc+2][lr] = pa.z; As[lc+3][lr] = pa.w;
        Bs[lc+0][lr] = pb.x; Bs[lc+1][lr] = pb.y;
        Bs[lc+2][lr] = pb.z; Bs[lc+3][lr] = pb.w;
        __syncthreads();

        if (k0 + GBK < K) {             // prefetch next tile under compute
            pa = *(const float4*)(Ag + k0 + GBK);
            pb = *(const float4*)(Bg + k0 + GBK);
        }

#pragma unroll
        for (int k = 0; k < GBK; k++) {
            alignas(16) float a[8];
            alignas(16) float b[8];
            *(float4*)&a[0] = *(const float4*)&As[k][ty*4];
            *(float4*)&a[4] = *(const float4*)&As[k][64 + ty*4];
            *(float4*)&b[0] = *(const float4*)&Bs[k][tx*4];
            *(float4*)&b[4] = *(const float4*)&Bs[k][64 + tx*4];
#pragma unroll
            for (int i = 0; i < 8; i++)
#pragma unroll
                for (int j = 0; j < 8; j++)
                    acc[i][j] += a[i] * b[j];
        }
        __syncthreads();
    }

#pragma unroll
    for (int ih = 0; ih < 2; ih++)
#pragma unroll
        for (int i = 0; i < 4; i++) {
            const int row = bm + ih*64 + ty*4 + i;
#pragma unroll
            for (int jh = 0; jh < 2; jh++) {
                const int col = bn + jh*64 + tx*4;
                float4 v;
                v.x = acc[ih*4+i][jh*4+0]; v.y = acc[ih*4+i][jh*4+1];
                v.z = acc[ih*4+i][jh*4+2]; v.w = acc[ih*4+i][jh*4+3];
                *(float4*)&C[(size_t)row * N + col] = v;
            }
        }
}

// =================================================================
// RoPE (matches reference: pairs (2i, 2i+1), freq = theta^(-i/64))
// double-precision phase: more accurate than the fp32 reference.
// =================================================================
__global__ void rope_kernel(float* __restrict__ X, int n_heads, int total)
{
    int idx = blockIdx.x * blockDim.x + threadIdx.x;
    if (idx >= total) return;
    const int i    = idx & 63;
    const int rest = idx >> 6;
    const int h    = rest % n_heads;
    const int t    = rest / n_heads;

    float* p = X + ((size_t)t * n_heads + h) * HD + 2*i;

    const double ang = (double)t * pow(500000.0, -(double)i / 64.0);
    const double c = cos(ang), s = sin(ang);
    const double e = (double)p[0], o = (double)p[1];
    p[0] = (float)(e*c - o*s);
    p[1] = (float)(e*s + o*c);
}

// =================================================================
// Flash attention (causal, GQA 4:1). BQ = BK = 64, head_dim = 128.
// All tiles in natural [row][128] layout; K tile XOR-swizzled at 16B
// granularity so strided-row float4 reads are bank-conflict-free.
// =================================================================
#define BQ  64
#define BKT 64
#define PSTRIDE 68

__device__ __forceinline__ int kswz(int r, int g) {
    // float index of 16B group g in row r, 3-bit XOR swizzle
    return r * HD + ((g ^ ((r >> 2) & 7)) << 2);
}

__global__ __launch_bounds__(256, 1)
void flash_kernel(const float* __restrict__ Q, const float* __restrict__ K,
                  const float* __restrict__ V, float* __restrict__ O)
{
    extern __shared__ float sm[];
    float* Qs = sm;                 // [64][128] natural
    float* Ks = Qs + BQ  * HD;      // [64][128] swizzled
    float* Vs = Ks + BKT * HD;      // [64][128] natural
    float* Ps = Vs + BKT * HD;      // [64][PSTRIDE]

    const int qb  = blockIdx.x;
    const int h   = blockIdx.y;
    const int kvh = h >> 2;
    const int tid = threadIdx.x;
    const int tx  = tid & 15;       // S cols tx*4.., O cols tx*8..
    const int ty  = tid >> 4;       // S/O rows ty*4..

    // ---- load Q tile (once) ----
    const float* Qg = Q + (size_t)qb * BQ * DIM + h * HD;
#pragma unroll
    for (int it = 0; it < 8; it++) {
        int i = tid + it * 256;
        int r = i >> 5, g = i & 31;
        *(float4*)&Qs[r * HD + g * 4] =
            *(const float4*)(Qg + (size_t)r * DIM + g * 4);
    }

    float m[4], l[4], acc[4][8];
#pragma unroll
    for (int i = 0; i < 4; i++) {
        m[i] = -1e30f; l[i] = 0.f;
#pragma unroll
        for (int j = 0; j < 8; j++) acc[i][j] = 0.f;
    }
    const float scale = 0.08838834764831845f;  // 1/sqrt(128)

    for (int kb = 0; kb <= qb; kb++) {
        __syncthreads();   // prior iter done with Ks/Vs/Ps; Q load done (iter 0)

        // ---- load K (swizzled) + V (natural) ----
        const float* Kg = K + (size_t)kb * BKT * KVDIM + kvh * HD;
        const float* Vg = V + (size_t)kb * BKT * KVDIM + kvh * HD;
#pragma unroll
        for (int it = 0; it < 8; it++) {
            int i = tid + it * 256;
            int r = i >> 5, g = i & 31;
            *(float4*)&Ks[kswz(r, g)]      = *(const float4*)(Kg + (size_t)r * KVDIM + g * 4);
            *(float4*)&Vs[r * HD + g * 4]  = *(const float4*)(Vg + (size_t)r * KVDIM + g * 4);
        }
        __syncthreads();

        // ---- S = Q K^T (4x4 per thread) ----
        float s[4][4];
#pragma unroll
        for (int i = 0; i < 4; i++)
#pragma unroll
            for (int j = 0; j < 4; j++) s[i][j] = 0.f;

#pragma unroll 8
        for (int g = 0; g < 32; g++) {
            float4 q0 = *(const float4*)&Qs[(ty*4+0) * HD + g*4];
            float4 q1 = *(const float4*)&Qs[(ty*4+1) * HD + g*4];
            float4 q2 = *(const float4*)&Qs[(ty*4+2) * HD + g*4];
            float4 q3 = *(const float4*)&Qs[(ty*4+3) * HD + g*4];
            float4 k0 = *(const float4*)&Ks[kswz(tx*4+0, g)];
            float4 k1 = *(const float4*)&Ks[kswz(tx*4+1, g)];
            float4 k2 = *(const float4*)&Ks[kswz(tx*4+2, g)];
            float4 k3 = *(const float4*)&Ks[kswz(tx*4+3, g)];
            float4 qv[4] = {q0, q1, q2, q3};
            float4 kv[4] = {k0, k1, k2, k3};
#pragma unroll
            for (int i = 0; i < 4; i++)
#pragma unroll
                for (int j = 0; j < 4; j++)
                    s[i][j] += qv[i].x*kv[j].x + qv[i].y*kv[j].y
                             + qv[i].z*kv[j].z + qv[i].w*kv[j].w;
        }

        // ---- scale + causal mask (only diagonal block is partial) ----
#pragma unroll
        for (int i = 0; i < 4; i++)
#pragma unroll
            for (int j = 0; j < 4; j++) s[i][j] *= scale;
        if (kb == qb) {
#pragma unroll
            for (int i = 0; i < 4; i++)
#pragma unroll
                for (int j = 0; j < 4; j++)
                    if (tx*4 + j > ty*4 + i) s[i][j] = -1e30f;
        }

        // ---- online softmax (row reductions over the 16-lane tx group) ----
#pragma unroll
        for (int i = 0; i < 4; i++) {
            float rm = fmaxf(fmaxf(s[i][0], s[i][1]), fmaxf(s[i][2], s[i][3]));
#pragma unroll
            for (int o = 8; o > 0; o >>= 1)
                rm = fmaxf(rm, __shfl_xor_sync(0xffffffffu, rm, o, 16));
            const float mn    = fmaxf(m[i], rm);
            const float alpha = __expf(m[i] - mn);
            float rs = 0.f;
#pragma unroll
            for (int j = 0; j < 4; j++) { s[i][j] = __expf(s[i][j] - mn); rs += s[i][j]; }
#pragma unroll
            for (int o = 8; o > 0; o >>= 1)
                rs += __shfl_xor_sync(0xffffffffu, rs, o, 16);
            l[i] = l[i] * alpha + rs;
            m[i] = mn;
#pragma unroll
            for (int j = 0; j < 8; j++) acc[i][j] *= alpha;
#pragma unroll
            for (int j = 0; j < 4; j++)
                Ps[(ty*4 + i) * PSTRIDE + tx*4 + j] = s[i][j];
        }
        __syncthreads();

        // ---- O += P @ V  (rows ty*4.., cols tx*8..) ----
#pragma unroll 4
        for (int kk = 0; kk < BKT; kk++) {
            float p[4];
#pragma unroll
            for (int i = 0; i < 4; i++) p[i] = Ps[(ty*4 + i) * PSTRIDE + kk];
            float4 v0 = *(const float4*)&Vs[kk * HD + tx*8];
            float4 v1 = *(const float4*)&Vs[kk * HD + tx*8 + 4];
#pragma unroll
            for (int i = 0; i < 4; i++) {
                acc[i][0] += p[i]*v0.x; acc[i][1] += p[i]*v0.y;
                acc[i][2] += p[i]*v0.z; acc[i][3] += p[i]*v0.w;
                acc[i][4] += p[i]*v1.x; acc[i][5] += p[i]*v1.y;
                acc[i][6] += p[i]*v1.z; acc[i][7] += p[i]*v1.w;
            }
        }
    }

    // ---- epilogue ----
#pragma unroll
    for (int i = 0; i < 4; i++) {
        const float inv = 1.0f / l[i];
        const int row = qb * BQ + ty*4 + i;
        float* Op = O + (size_t)row * DIM + h * HD + tx*8;
        float4 o0, o1;
        o0.x = acc[i][0]*inv; o0.y = acc[i][1]*inv;
        o0.z = acc[i][2]*inv; o0.w = acc[i][3]*inv;
        o1.x = acc[i][4]*inv; o1.y = acc[i][5]*inv;
        o1.z = acc[i][6]*inv; o1.w = acc[i][7]*inv;
        *(float4*)Op       = o0;
        *(float4*)(Op + 4) = o1;
    }
}

// =================================================================
// launch
// =================================================================
#define FLASH_SMEM ((3 * BQ * HD + BQ * PSTRIDE) * (int)sizeof(float))

extern "C" void kernel_launch(void* const* d_in, const int* in_sizes, int n_in,
                              void* d_out, int out_size)
{
    const float* x  = (const float*)d_in[0];
    const float* wq = (const float*)d_in[1];
    const float* wk = (const float*)d_in[2];
    const float* wv = (const float*)d_in[3];
    const float* wo = (const float*)d_in[4];
    float* out = (float*)d_out;

    float *Q, *K, *V, *A;
    cudaGetSymbolAddress((void**)&Q, g_Q);
    cudaGetSymbolAddress((void**)&K, g_K);
    cudaGetSymbolAddress((void**)&V, g_V);
    cudaGetSymbolAddress((void**)&A, g_A);

    // projections
    gemm_nt<<<dim3(DIM/GBN,   SEQ/GBM), 256>>>(x, wq, Q, SEQ, DIM,   DIM);
    gemm_nt<<<dim3(KVDIM/GBN, SEQ/GBM), 256>>>(x, wk, K, SEQ, KVDIM, DIM);
    gemm_nt<<<dim3(KVDIM/GBN, SEQ/GBM), 256>>>(x, wv, V, SEQ, KVDIM, DIM);

    // RoPE
    {
        int totq = SEQ * NH * (HD/2);
        int totk = SEQ * NKV * (HD/2);
        rope_kernel<<<(totq + 255)/256, 256>>>(Q, NH,  totq);
        rope_kernel<<<(totk + 255)/256, 256>>>(K, NKV, totk);
    }

    // attention
    cudaFuncSetAttribute(flash_kernel,
                         cudaFuncAttributeMaxDynamicSharedMemorySize, FLASH_SMEM);
    flash_kernel<<<dim3(SEQ/BQ, NH), 256, FLASH_SMEM>>>(Q, K, V, A);

    // output projection
    gemm_nt<<<dim3(DIM/GBN, SEQ/GBM), 256>>>(A, wo, out, SEQ, DIM, DIM);
}

// round 11
// speedup vs baseline: 1.4097x; 1.4097x over previous
#include <cuda_runtime.h>
#include <math.h>
#include <stdint.h>

#define SEQ   2048
#define DIM   4096
#define NH    32
#define NKV   8
#define HD    128
#define KVDIM (NKV*HD)   /* 1024 */

// ---------------- scratch (no allocations allowed) ----------------
__device__ float  g_Q[SEQ*DIM];
__device__ float  g_K[SEQ*KVDIM];
__device__ float  g_V[SEQ*KVDIM];
__device__ float  g_A[SEQ*DIM];
__device__ float2 g_cs[SEQ*64];     // RoPE cos/sin table

// =================================================================
// portable PTX helpers (family-safe: compiles under compute_103)
// =================================================================
__device__ __forceinline__ uint32_t s2u(const void* p) {
    uint32_t a;
    asm("{ .reg .u64 t; cvta.to.shared.u64 t, %1; cvt.u32.u64 %0, t; }"
        : "=r"(a) : "l"(p));
    return a;
}
__device__ __forceinline__ void cp16(uint32_t dst, const void* src) {
    asm volatile("cp.async.cg.shared.global [%0], [%1], 16;"
                 :: "r"(dst), "l"(src) : "memory");
}
__device__ __forceinline__ void cp_commit() {
    asm volatile("cp.async.commit_group;" ::: "memory");
}
template <int N>
__device__ __forceinline__ void cp_wait() {
    asm volatile("cp.async.wait_group %0;" :: "n"(N) : "memory");
}
// D += A*B  (m16n8k8, tf32 inputs, fp32 accum)
__device__ __forceinline__ void mma_tf32(float* c, const uint32_t* a, const uint32_t* b) {
    asm volatile(
        "mma.sync.aligned.m16n8k8.row.col.f32.tf32.tf32.f32 "
        "{%0,%1,%2,%3}, {%4,%5,%6,%7}, {%8,%9}, {%0,%1,%2,%3};"
        : "+f"(c[0]), "+f"(c[1]), "+f"(c[2]), "+f"(c[3])
        : "r"(a[0]), "r"(a[1]), "r"(a[2]), "r"(a[3]), "r"(b[0]), "r"(b[1]));
}
// v -> (hi, lo) tf32 pair: hi = rna(v), lo = rna(v - hi)
__device__ __forceinline__ void split_tf32(float v, uint32_t& hi, uint32_t& lo) {
    uint32_t h;
    asm("cvt.rna.tf32.f32 %0, %1;" : "=r"(h) : "f"(v));
    const float lf = v - __uint_as_float(h);
    uint32_t l;
    asm("cvt.rna.tf32.f32 %0, %1;" : "=r"(l) : "f"(lf));
    hi = h; lo = l;
}

// =================================================================
// 3xTF32 GEMM: C[M,N] = A[M,K] * B[N,K]^T (row-major, K contig)
// 128x128 CTA tile, BK=32, 256 threads (8 warps 2x4), warp tile 64x32.
// cp.async double-buffered raw fp32; split to (hi,lo) at fragment load;
// acc += lo*hi + hi*lo + hi*hi  (fp32-accurate).
// =================================================================
#define GST 36                                  /* smem row stride (floats) */
#define GBUF (128 * GST)                        /* one tile: 4608 floats */
#define G_SMEM (4 * GBUF * (int)sizeof(float))  /* 2 bufs x (A+B) = 73728 B */

__global__ __launch_bounds__(256, 1)
void gemm_tc(const float* __restrict__ A, const float* __restrict__ B,
             float* __restrict__ C, int M, int N, int K)
{
    extern __shared__ float sm[];
    const uint32_t sb = s2u(sm);

    const int tid = threadIdx.x;
    const int wid = tid >> 5, lane = tid & 31;
    const int g = lane >> 2, tig = lane & 3;
    const int warp_m = wid >> 2, warp_n = wid & 3;
    const int bm = blockIdx.y * 128, bn = blockIdx.x * 128;

    auto load_chunk = [&](int kc, int buf) {
        const float* Ap = A + (size_t)bm * K + kc * 32;
        const float* Bp = B + (size_t)bn * K + kc * 32;
        const uint32_t ab = sb + (uint32_t)(2 * buf)     * GBUF * 4;
        const uint32_t bb = sb + (uint32_t)(2 * buf + 1) * GBUF * 4;
#pragma unroll
        for (int t = 0; t < 4; t++) {
            int i = tid + t * 256;
            int r = i >> 3, c = (i & 7) * 4;
            uint32_t so = (uint32_t)(r * GST + c) * 4;
            cp16(ab + so, Ap + (size_t)r * K + c);
            cp16(bb + so, Bp + (size_t)r * K + c);
        }
        cp_commit();
    };

    float acc[4][4][4];
#pragma unroll
    for (int i = 0; i < 4; i++)
#pragma unroll
        for (int j = 0; j < 4; j++)
#pragma unroll
            for (int q = 0; q < 4; q++) acc[i][j][q] = 0.f;

    const int NC = K >> 5;
    load_chunk(0, 0);

    for (int kc = 0; kc < NC; kc++) {
        if (kc + 1 < NC) { load_chunk(kc + 1, (kc + 1) & 1); cp_wait<1>(); }
        else             { cp_wait<0>(); }
        __syncthreads();

        const float* As = sm + (2 * (kc & 1))     * GBUF;
        const float* Bs = sm + (2 * (kc & 1) + 1) * GBUF;

#pragma unroll
        for (int ks = 0; ks < 4; ks++) {
            const int k0 = ks * 8;
            uint32_t ah[4][4], al[4][4], bh[4][2], bl[4][2];
#pragma unroll
            for (int tm = 0; tm < 4; tm++) {
                const int r0 = warp_m * 64 + tm * 16 + g;
                split_tf32(As[ r0      * GST + k0 + tig    ], ah[tm][0], al[tm][0]);
                split_tf32(As[(r0 + 8) * GST + k0 + tig    ], ah[tm][1], al[tm][1]);
                split_tf32(As[ r0      * GST + k0 + tig + 4], ah[tm][2], al[tm][2]);
                split_tf32(As[(r0 + 8) * GST + k0 + tig + 4], ah[tm][3], al[tm][3]);
            }
#pragma unroll
            for (int tn = 0; tn < 4; tn++) {
                const int r0 = warp_n * 32 + tn * 8 + g;
                split_tf32(Bs[r0 * GST + k0 + tig    ], bh[tn][0], bl[tn][0]);
                split_tf32(Bs[r0 * GST + k0 + tig + 4], bh[tn][1], bl[tn][1]);
            }
#pragma unroll
            for (int tm = 0; tm < 4; tm++)
#pragma unroll
                for (int tn = 0; tn < 4; tn++) {
                    mma_tf32(acc[tm][tn], al[tm], bh[tn]);   // small terms first
                    mma_tf32(acc[tm][tn], ah[tm], bl[tn]);
                    mma_tf32(acc[tm][tn], ah[tm], bh[tn]);
                }
        }
        __syncthreads();
    }

    // ---- epilogue ----
#pragma unroll
    for (int tm = 0; tm < 4; tm++) {
        const int row = bm + warp_m * 64 + tm * 16 + g;
#pragma unroll
        for (int tn = 0; tn < 4; tn++) {
            const int col = bn + warp_n * 32 + tn * 8 + tig * 2;
            *(float2*)&C[(size_t) row      * N + col] =
                make_float2(acc[tm][tn][0], acc[tm][tn][1]);
            *(float2*)&C[(size_t)(row + 8) * N + col] =
                make_float2(acc[tm][tn][2], acc[tm][tn][3]);
        }
    }
}

// =================================================================
// RoPE: precompute (cos,sin) table once (double precision), then a
// trivial memory-bound apply (Q and K fused into one launch).
// =================================================================
__global__ void rope_table()
{
    int idx = blockIdx.x * blockDim.x + threadIdx.x;
    if (idx >= SEQ * 64) return;
    const int t = idx >> 6, i = idx & 63;
    const double ang = (double)t * pow(500000.0, -(double)i / 64.0);
    g_cs[idx] = make_float2((float)cos(ang), (float)sin(ang));
}

#define ROPE_TOTQ (SEQ * NH  * 64)
#define ROPE_TOTK (SEQ * NKV * 64)

__global__ void rope_apply(float* __restrict__ Xq, float* __restrict__ Xk)
{
    int idx = blockIdx.x * blockDim.x + threadIdx.x;
    float* X; int n_heads;
    if (idx < ROPE_TOTQ) { X = Xq; n_heads = NH; }
    else {
        idx -= ROPE_TOTQ;
        if (idx >= ROPE_TOTK) return;
        X = Xk; n_heads = NKV;
    }
    const int i    = idx & 63;
    const int rest = idx >> 6;
    const int h    = rest % n_heads;
    const int t    = rest / n_heads;

    const float2 cs = g_cs[(t << 6) | i];
    float2* p = (float2*)(X + (((size_t)t * n_heads + h) << 7) + 2 * i);
    const float2 v = *p;
    *p = make_float2(v.x * cs.x - v.y * cs.y, v.x * cs.y + v.y * cs.x);
}

// =================================================================
// Flash attention (causal, GQA 4:1), fp32 SIMT — R6-proven.
// =================================================================
#define BQ  64
#define BKT 64
#define PSTRIDE 68

__device__ __forceinline__ int kswz(int r, int g) {
    return r * HD + ((g ^ ((r >> 2) & 7)) << 2);
}

__global__ __launch_bounds__(256, 1)
void flash_kernel(const float* __restrict__ Q, const float* __restrict__ K,
                  const float* __restrict__ V, float* __restrict__ O)
{
    extern __shared__ float sm[];
    float* Qs = sm;
    float* Ks = Qs + BQ  * HD;
    float* Vs = Ks + BKT * HD;
    float* Ps = Vs + BKT * HD;

    const int qb  = blockIdx.x;
    const int h   = blockIdx.y;
    const int kvh = h >> 2;
    const int tid = threadIdx.x;
    const int tx  = tid & 15;
    const int ty  = tid >> 4;

    const float* Qg = Q + (size_t)qb * BQ * DIM + h * HD;
#pragma unroll
    for (int it = 0; it < 8; it++) {
        int i = tid + it * 256;
        int r = i >> 5, g = i & 31;
        *(float4*)&Qs[r * HD + g * 4] =
            *(const float4*)(Qg + (size_t)r * DIM + g * 4);
    }

    float m[4], l[4], acc[4][8];
#pragma unroll
    for (int i = 0; i < 4; i++) {
        m[i] = -1e30f; l[i] = 0.f;
#pragma unroll
        for (int j = 0; j < 8; j++) acc[i][j] = 0.f;
    }
    const float scale = 0.08838834764831845f;

    for (int kb = 0; kb <= qb; kb++) {
        __syncthreads();

        const float* Kg = K + (size_t)kb * BKT * KVDIM + kvh * HD;
        const float* Vg = V + (size_t)kb * BKT * KVDIM + kvh * HD;
#pragma unroll
        for (int it = 0; it < 8; it++) {
            int i = tid + it * 256;
            int r = i >> 5, g = i & 31;
            *(float4*)&Ks[kswz(r, g)]     = *(const float4*)(Kg + (size_t)r * KVDIM + g * 4);
            *(float4*)&Vs[r * HD + g * 4] = *(const float4*)(Vg + (size_t)r * KVDIM + g * 4);
        }
        __syncthreads();

        float s[4][4];
#pragma unroll
        for (int i = 0; i < 4; i++)
#pragma unroll
            for (int j = 0; j < 4; j++) s[i][j] = 0.f;

#pragma unroll 8
        for (int g = 0; g < 32; g++) {
            float4 q0 = *(const float4*)&Qs[(ty*4+0) * HD + g*4];
            float4 q1 = *(const float4*)&Qs[(ty*4+1) * HD + g*4];
            float4 q2 = *(const float4*)&Qs[(ty*4+2) * HD + g*4];
            float4 q3 = *(const float4*)&Qs[(ty*4+3) * HD + g*4];
            float4 k0 = *(const float4*)&Ks[kswz(tx*4+0, g)];
            float4 k1 = *(const float4*)&Ks[kswz(tx*4+1, g)];
            float4 k2 = *(const float4*)&Ks[kswz(tx*4+2, g)];
            float4 k3 = *(const float4*)&Ks[kswz(tx*4+3, g)];
            float4 qv[4] = {q0, q1, q2, q3};
            float4 kv[4] = {k0, k1, k2, k3};
#pragma unroll
            for (int i = 0; i < 4; i++)
#pragma unroll
                for (int j = 0; j < 4; j++)
                    s[i][j] += qv[i].x*kv[j].x + qv[i].y*kv[j].y
                             + qv[i].z*kv[j].z + qv[i].w*kv[j].w;
        }

#pragma unroll
        for (int i = 0; i < 4; i++)
#pragma unroll
            for (int j = 0; j < 4; j++) s[i][j] *= scale;
        if (kb == qb) {
#pragma unroll
            for (int i = 0; i < 4; i++)
#pragma unroll
                for (int j = 0; j < 4; j++)
                    if (tx*4 + j > ty*4 + i) s[i][j] = -1e30f;
        }

#pragma unroll
        for (int i = 0; i < 4; i++) {
            float rm = fmaxf(fmaxf(s[i][0], s[i][1]), fmaxf(s[i][2], s[i][3]));
#pragma unroll
            for (int o = 8; o > 0; o >>= 1)
                rm = fmaxf(rm, __shfl_xor_sync(0xffffffffu, rm, o, 16));
            const float mn    = fmaxf(m[i], rm);
            const float alpha = __expf(m[i] - mn);
            float rs = 0.f;
#pragma unroll
            for (int j = 0; j < 4; j++) { s[i][j] = __expf(s[i][j] - mn); rs += s[i][j]; }
#pragma unroll
            for (int o = 8; o > 0; o >>= 1)
                rs += __shfl_xor_sync(0xffffffffu, rs, o, 16);
            l[i] = l[i] * alpha + rs;
            m[i] = mn;
#pragma unroll
            for (int j = 0; j < 8; j++) acc[i][j] *= alpha;
#pragma unroll
            for (int j = 0; j < 4; j++)
                Ps[(ty*4 + i) * PSTRIDE + tx*4 + j] = s[i][j];
        }
        __syncthreads();

#pragma unroll 4
        for (int kk = 0; kk < BKT; kk++) {
            float p[4];
#pragma unroll
            for (int i = 0; i < 4; i++) p[i] = Ps[(ty*4 + i) * PSTRIDE + kk];
            float4 v0 = *(const float4*)&Vs[kk * HD + tx*8];
            float4 v1 = *(const float4*)&Vs[kk * HD + tx*8 + 4];
#pragma unroll
            for (int i = 0; i < 4; i++) {
                acc[i][0] += p[i]*v0.x; acc[i][1] += p[i]*v0.y;
                acc[i][2] += p[i]*v0.z; acc[i][3] += p[i]*v0.w;
                acc[i][4] += p[i]*v1.x; acc[i][5] += p[i]*v1.y;
                acc[i][6] += p[i]*v1.z; acc[i][7] += p[i]*v1.w;
            }
        }
    }

#pragma unroll
    for (int i = 0; i < 4; i++) {
        const float inv = 1.0f / l[i];
        const int row = qb * BQ + ty*4 + i;
        float* Op = O + (size_t)row * DIM + h * HD + tx*8;
        float4 o0, o1;
        o0.x = acc[i][0]*inv; o0.y = acc[i][1]*inv;
        o0.z = acc[i][2]*inv; o0.w = acc[i][3]*inv;
        o1.x = acc[i][4]*inv; o1.y = acc[i][5]*inv;
        o1.z = acc[i][6]*inv; o1.w = acc[i][7]*inv;
        *(float4*)Op       = o0;
        *(float4*)(Op + 4) = o1;
    }
}

// =================================================================
// launch
// =================================================================
#define FLASH_SMEM ((3 * BQ * HD + BQ * PSTRIDE) * (int)sizeof(float))

extern "C" void kernel_launch(void* const* d_in, const int* in_sizes, int n_in,
                              void* d_out, int out_size)
{
    const float* x  = (const float*)d_in[0];
    const float* wq = (const float*)d_in[1];
    const float* wk = (const float*)d_in[2];
    const float* wv = (const float*)d_in[3];
    const float* wo = (const float*)d_in[4];
    float* out = (float*)d_out;

    float *Q, *K, *V, *A;
    cudaGetSymbolAddress((void**)&Q, g_Q);
    cudaGetSymbolAddress((void**)&K, g_K);
    cudaGetSymbolAddress((void**)&V, g_V);
    cudaGetSymbolAddress((void**)&A, g_A);

    cudaFuncSetAttribute(gemm_tc,
                         cudaFuncAttributeMaxDynamicSharedMemorySize, G_SMEM);
    cudaFuncSetAttribute(flash_kernel,
                         cudaFuncAttributeMaxDynamicSharedMemorySize, FLASH_SMEM);

    // RoPE table (independent of projections)
    rope_table<<<(SEQ * 64 + 255) / 256, 256>>>();

    // projections (3xTF32 mma.sync)
    gemm_tc<<<dim3(DIM  /128, SEQ/128), 256, G_SMEM>>>(x, wq, Q, SEQ, DIM,   DIM);
    gemm_tc<<<dim3(KVDIM/128, SEQ/128), 256, G_SMEM>>>(x, wk, K, SEQ, KVDIM, DIM);
    gemm_tc<<<dim3(KVDIM/128, SEQ/128), 256, G_SMEM>>>(x, wv, V, SEQ, KVDIM, DIM);

    // RoPE apply (Q + K fused)
    rope_apply<<<(ROPE_TOTQ + ROPE_TOTK + 255) / 256, 256>>>(Q, K);

    // attention
    flash_kernel<<<dim3(SEQ/BQ, NH), 256, FLASH_SMEM>>>(Q, K, V, A);

    // output projection (3xTF32 mma.sync)
    gemm_tc<<<dim3(DIM/128, SEQ/128), 256, G_SMEM>>>(A, wo, out, SEQ, DIM, DIM);
}

// round 12
// speedup vs baseline: 1.5178x; 1.0766x over previous
#include <cuda_runtime.h>
#include <math.h>
#include <stdint.h>

#define SEQ   2048
#define DIM   4096
#define NH    32
#define NKV   8
#define HD    128
#define KVDIM (NKV*HD)   /* 1024 */

// ---------------- scratch (no allocations allowed) ----------------
__device__ float  g_Q[SEQ*DIM];
__device__ float  g_K[SEQ*KVDIM];
__device__ float  g_V[SEQ*KVDIM];
__device__ float  g_A[SEQ*DIM];
__device__ float2 g_cs[SEQ*64];     // RoPE cos/sin table

// =================================================================
// portable PTX helpers (family-safe: compiles under compute_103)
// =================================================================
__device__ __forceinline__ uint32_t s2u(const void* p) {
    uint32_t a;
    asm("{ .reg .u64 t; cvta.to.shared.u64 t, %1; cvt.u32.u64 %0, t; }"
        : "=r"(a) : "l"(p));
    return a;
}
__device__ __forceinline__ void cp16(uint32_t dst, const void* src) {
    asm volatile("cp.async.cg.shared.global [%0], [%1], 16;"
                 :: "r"(dst), "l"(src) : "memory");
}
__device__ __forceinline__ void cp_commit() {
    asm volatile("cp.async.commit_group;" ::: "memory");
}
template <int N>
__device__ __forceinline__ void cp_wait() {
    asm volatile("cp.async.wait_group %0;" :: "n"(N) : "memory");
}
// D += A*B  (m16n8k8, tf32 inputs, fp32 accum)
__device__ __forceinline__ void mma_tf32(float* c, const uint32_t* a, const uint32_t* b) {
    asm volatile(
        "mma.sync.aligned.m16n8k8.row.col.f32.tf32.tf32.f32 "
        "{%0,%1,%2,%3}, {%4,%5,%6,%7}, {%8,%9}, {%0,%1,%2,%3};"
        : "+f"(c[0]), "+f"(c[1]), "+f"(c[2]), "+f"(c[3])
        : "r"(a[0]), "r"(a[1]), "r"(a[2]), "r"(a[3]), "r"(b[0]), "r"(b[1]));
}
// v -> (hi, lo): mask-based tf32 split, no slow F2F cvt.
// hi = v with low 13 mantissa bits zeroed (exactly representable in tf32);
// v - hi is Sterbenz-exact; lo truncated the same way. Residual ~2^-21 |v|.
__device__ __forceinline__ void split_tf32(float v, uint32_t& hi, uint32_t& lo) {
    const uint32_t hb = __float_as_uint(v) & 0xFFFFE000u;
    const float lf = v - __uint_as_float(hb);
    hi = hb;
    lo = __float_as_uint(lf) & 0xFFFFE000u;
}

// =================================================================
// 3xTF32 GEMM: C[M,N] = A[M,K] * B[N,K]^T (row-major, K contig)
// 128x128 CTA tile, BK=32, 256 threads (8 warps 2x4), warp tile 64x32.
// cp.async double-buffered raw fp32; mask-split at fragment load;
// pass-major MMA order: acc += lo*hi, then hi*lo, then hi*hi.
// =================================================================
#define GST 36                                  /* smem row stride (floats) */
#define GBUF (128 * GST)                        /* one tile: 4608 floats */
#define G_SMEM (4 * GBUF * (int)sizeof(float))  /* 2 bufs x (A+B) = 73728 B */

__global__ __launch_bounds__(256, 1)
void gemm_tc(const float* __restrict__ A, const float* __restrict__ B,
             float* __restrict__ C, int M, int N, int K)
{
    extern __shared__ float sm[];
    const uint32_t sb = s2u(sm);

    const int tid = threadIdx.x;
    const int wid = tid >> 5, lane = tid & 31;
    const int g = lane >> 2, tig = lane & 3;
    const int warp_m = wid >> 2, warp_n = wid & 3;
    const int bm = blockIdx.y * 128, bn = blockIdx.x * 128;

    auto load_chunk = [&](int kc, int buf) {
        const float* Ap = A + (size_t)bm * K + kc * 32;
        const float* Bp = B + (size_t)bn * K + kc * 32;
        const uint32_t ab = sb + (uint32_t)(2 * buf)     * GBUF * 4;
        const uint32_t bb = sb + (uint32_t)(2 * buf + 1) * GBUF * 4;
#pragma unroll
        for (int t = 0; t < 4; t++) {
            int i = tid + t * 256;
            int r = i >> 3, c = (i & 7) * 4;
            uint32_t so = (uint32_t)(r * GST + c) * 4;
            cp16(ab + so, Ap + (size_t)r * K + c);
            cp16(bb + so, Bp + (size_t)r * K + c);
        }
        cp_commit();
    };

    float acc[4][4][4];
#pragma unroll
    for (int i = 0; i < 4; i++)
#pragma unroll
        for (int j = 0; j < 4; j++)
#pragma unroll
            for (int q = 0; q < 4; q++) acc[i][j][q] = 0.f;

    const int NC = K >> 5;
    load_chunk(0, 0);

    for (int kc = 0; kc < NC; kc++) {
        if (kc + 1 < NC) { load_chunk(kc + 1, (kc + 1) & 1); cp_wait<1>(); }
        else             { cp_wait<0>(); }
        __syncthreads();

        const float* As = sm + (2 * (kc & 1))     * GBUF;
        const float* Bs = sm + (2 * (kc & 1) + 1) * GBUF;

#pragma unroll
        for (int ks = 0; ks < 4; ks++) {
            const int k0 = ks * 8;
            uint32_t ah[4][4], al[4][4], bh[4][2], bl[4][2];
#pragma unroll
            for (int tm = 0; tm < 4; tm++) {
                const int r0 = warp_m * 64 + tm * 16 + g;
                split_tf32(As[ r0      * GST + k0 + tig    ], ah[tm][0], al[tm][0]);
                split_tf32(As[(r0 + 8) * GST + k0 + tig    ], ah[tm][1], al[tm][1]);
                split_tf32(As[ r0      * GST + k0 + tig + 4], ah[tm][2], al[tm][2]);
                split_tf32(As[(r0 + 8) * GST + k0 + tig + 4], ah[tm][3], al[tm][3]);
            }
#pragma unroll
            for (int tn = 0; tn < 4; tn++) {
                const int r0 = warp_n * 32 + tn * 8 + g;
                split_tf32(Bs[r0 * GST + k0 + tig    ], bh[tn][0], bl[tn][0]);
                split_tf32(Bs[r0 * GST + k0 + tig + 4], bh[tn][1], bl[tn][1]);
            }
            // pass-major order: long dependency distance on each accumulator
#pragma unroll
            for (int tm = 0; tm < 4; tm++)
#pragma unroll
                for (int tn = 0; tn < 4; tn++)
                    mma_tf32(acc[tm][tn], al[tm], bh[tn]);
#pragma unroll
            for (int tm = 0; tm < 4; tm++)
#pragma unroll
                for (int tn = 0; tn < 4; tn++)
                    mma_tf32(acc[tm][tn], ah[tm], bl[tn]);
#pragma unroll
            for (int tm = 0; tm < 4; tm++)
#pragma unroll
                for (int tn = 0; tn < 4; tn++)
                    mma_tf32(acc[tm][tn], ah[tm], bh[tn]);
        }
        __syncthreads();
    }

    // ---- epilogue ----
#pragma unroll
    for (int tm = 0; tm < 4; tm++) {
        const int row = bm + warp_m * 64 + tm * 16 + g;
#pragma unroll
        for (int tn = 0; tn < 4; tn++) {
            const int col = bn + warp_n * 32 + tn * 8 + tig * 2;
            *(float2*)&C[(size_t) row      * N + col] =
                make_float2(acc[tm][tn][0], acc[tm][tn][1]);
            *(float2*)&C[(size_t)(row + 8) * N + col] =
                make_float2(acc[tm][tn][2], acc[tm][tn][3]);
        }
    }
}

// =================================================================
// RoPE: precompute (cos,sin) table once (double precision), then a
// trivial memory-bound apply (Q and K fused into one launch).
// =================================================================
__global__ void rope_table()
{
    int idx = blockIdx.x * blockDim.x + threadIdx.x;
    if (idx >= SEQ * 64) return;
    const int t = idx >> 6, i = idx & 63;
    const double ang = (double)t * pow(500000.0, -(double)i / 64.0);
    g_cs[idx] = make_float2((float)cos(ang), (float)sin(ang));
}

#define ROPE_TOTQ (SEQ * NH  * 64)
#define ROPE_TOTK (SEQ * NKV * 64)

__global__ void rope_apply(float* __restrict__ Xq, float* __restrict__ Xk)
{
    int idx = blockIdx.x * blockDim.x + threadIdx.x;
    float* X; int n_heads;
    if (idx < ROPE_TOTQ) { X = Xq; n_heads = NH; }
    else {
        idx -= ROPE_TOTQ;
        if (idx >= ROPE_TOTK) return;
        X = Xk; n_heads = NKV;
    }
    const int i    = idx & 63;
    const int rest = idx >> 6;
    const int h    = rest % n_heads;
    const int t    = rest / n_heads;

    const float2 cs = g_cs[(t << 6) | i];
    float2* p = (float2*)(X + (((size_t)t * n_heads + h) << 7) + 2 * i);
    const float2 v = *p;
    *p = make_float2(v.x * cs.x - v.y * cs.y, v.x * cs.y + v.y * cs.x);
}

// =================================================================
// Flash attention (causal, GQA 4:1), fp32 SIMT — R6-proven.
// =================================================================
#define BQ  64
#define BKT 64
#define PSTRIDE 68

__device__ __forceinline__ int kswz(int r, int g) {
    return r * HD + ((g ^ ((r >> 2) & 7)) << 2);
}

__global__ __launch_bounds__(256, 1)
void flash_kernel(const float* __restrict__ Q, const float* __restrict__ K,
                  const float* __restrict__ V, float* __restrict__ O)
{
    extern __shared__ float sm[];
    float* Qs = sm;
    float* Ks = Qs + BQ  * HD;
    float* Vs = Ks + BKT * HD;
    float* Ps = Vs + BKT * HD;

    const int qb  = blockIdx.x;
    const int h   = blockIdx.y;
    const int kvh = h >> 2;
    const int tid = threadIdx.x;
    const int tx  = tid & 15;
    const int ty  = tid >> 4;

    const float* Qg = Q + (size_t)qb * BQ * DIM + h * HD;
#pragma unroll
    for (int it = 0; it < 8; it++) {
        int i = tid + it * 256;
        int r = i >> 5, g = i & 31;
        *(float4*)&Qs[r * HD + g * 4] =
            *(const float4*)(Qg + (size_t)r * DIM + g * 4);
    }

    float m[4], l[4], acc[4][8];
#pragma unroll
    for (int i = 0; i < 4; i++) {
        m[i] = -1e30f; l[i] = 0.f;
#pragma unroll
        for (int j = 0; j < 8; j++) acc[i][j] = 0.f;
    }
    const float scale = 0.08838834764831845f;

    for (int kb = 0; kb <= qb; kb++) {
        __syncthreads();

        const float* Kg = K + (size_t)kb * BKT * KVDIM + kvh * HD;
        const float* Vg = V + (size_t)kb * BKT * KVDIM + kvh * HD;
#pragma unroll
        for (int it = 0; it < 8; it++) {
            int i = tid + it * 256;
            int r = i >> 5, g = i & 31;
            *(float4*)&Ks[kswz(r, g)]     = *(const float4*)(Kg + (size_t)r * KVDIM + g * 4);
            *(float4*)&Vs[r * HD + g * 4] = *(const float4*)(Vg + (size_t)r * KVDIM + g * 4);
        }
        __syncthreads();

        float s[4][4];
#pragma unroll
        for (int i = 0; i < 4; i++)
#pragma unroll
            for (int j = 0; j < 4; j++) s[i][j] = 0.f;

#pragma unroll 8
        for (int g = 0; g < 32; g++) {
            float4 q0 = *(const float4*)&Qs[(ty*4+0) * HD + g*4];
            float4 q1 = *(const float4*)&Qs[(ty*4+1) * HD + g*4];
            float4 q2 = *(const float4*)&Qs[(ty*4+2) * HD + g*4];
            float4 q3 = *(const float4*)&Qs[(ty*4+3) * HD + g*4];
            float4 k0 = *(const float4*)&Ks[kswz(tx*4+0, g)];
            float4 k1 = *(const float4*)&Ks[kswz(tx*4+1, g)];
            float4 k2 = *(const float4*)&Ks[kswz(tx*4+2, g)];
            float4 k3 = *(const float4*)&Ks[kswz(tx*4+3, g)];
            float4 qv[4] = {q0, q1, q2, q3};
            float4 kv[4] = {k0, k1, k2, k3};
#pragma unroll
            for (int i = 0; i < 4; i++)
#pragma unroll
                for (int j = 0; j < 4; j++)
                    s[i][j] += qv[i].x*kv[j].x + qv[i].y*kv[j].y
                             + qv[i].z*kv[j].z + qv[i].w*kv[j].w;
        }

#pragma unroll
        for (int i = 0; i < 4; i++)
#pragma unroll
            for (int j = 0; j < 4; j++) s[i][j] *= scale;
        if (kb == qb) {
#pragma unroll
            for (int i = 0; i < 4; i++)
#pragma unroll
                for (int j = 0; j < 4; j++)
                    if (tx*4 + j > ty*4 + i) s[i][j] = -1e30f;
        }

#pragma unroll
        for (int i = 0; i < 4; i++) {
            float rm = fmaxf(fmaxf(s[i][0], s[i][1]), fmaxf(s[i][2], s[i][3]));
#pragma unroll
            for (int o = 8; o > 0; o >>= 1)
                rm = fmaxf(rm, __shfl_xor_sync(0xffffffffu, rm, o, 16));
            const float mn    = fmaxf(m[i], rm);
            const float alpha = __expf(m[i] - mn);
            float rs = 0.f;
#pragma unroll
            for (int j = 0; j < 4; j++) { s[i][j] = __expf(s[i][j] - mn); rs += s[i][j]; }
#pragma unroll
            for (int o = 8; o > 0; o >>= 1)
                rs += __shfl_xor_sync(0xffffffffu, rs, o, 16);
            l[i] = l[i] * alpha + rs;
            m[i] = mn;
#pragma unroll
            for (int j = 0; j < 8; j++) acc[i][j] *= alpha;
#pragma unroll
            for (int j = 0; j < 4; j++)
                Ps[(ty*4 + i) * PSTRIDE + tx*4 + j] = s[i][j];
        }
        __syncthreads();

#pragma unroll 4
        for (int kk = 0; kk < BKT; kk++) {
            float p[4];
#pragma unroll
            for (int i = 0; i < 4; i++) p[i] = Ps[(ty*4 + i) * PSTRIDE + kk];
            float4 v0 = *(const float4*)&Vs[kk * HD + tx*8];
            float4 v1 = *(const float4*)&Vs[kk * HD + tx*8 + 4];
#pragma unroll
            for (int i = 0; i < 4; i++) {
                acc[i][0] += p[i]*v0.x; acc[i][1] += p[i]*v0.y;
                acc[i][2] += p[i]*v0.z; acc[i][3] += p[i]*v0.w;
                acc[i][4] += p[i]*v1.x; acc[i][5] += p[i]*v1.y;
                acc[i][6] += p[i]*v1.z; acc[i][7] += p[i]*v1.w;
            }
        }
    }

#pragma unroll
    for (int i = 0; i < 4; i++) {
        const float inv = 1.0f / l[i];
        const int row = qb * BQ + ty*4 + i;
        float* Op = O + (size_t)row * DIM + h * HD + tx*8;
        float4 o0, o1;
        o0.x = acc[i][0]*inv; o0.y = acc[i][1]*inv;
        o0.z = acc[i][2]*inv; o0.w = acc[i][3]*inv;
        o1.x = acc[i][4]*inv; o1.y = acc[i][5]*inv;
        o1.z = acc[i][6]*inv; o1.w = acc[i][7]*inv;
        *(float4*)Op       = o0;
        *(float4*)(Op + 4) = o1;
    }
}

// =================================================================
// launch
// =================================================================
#define FLASH_SMEM ((3 * BQ * HD + BQ * PSTRIDE) * (int)sizeof(float))

extern "C" void kernel_launch(void* const* d_in, const int* in_sizes, int n_in,
                              void* d_out, int out_size)
{
    const float* x  = (const float*)d_in[0];
    const float* wq = (const float*)d_in[1];
    const float* wk = (const float*)d_in[2];
    const float* wv = (const float*)d_in[3];
    const float* wo = (const float*)d_in[4];
    float* out = (float*)d_out;

    float *Q, *K, *V, *A;
    cudaGetSymbolAddress((void**)&Q, g_Q);
    cudaGetSymbolAddress((void**)&K, g_K);
    cudaGetSymbolAddress((void**)&V, g_V);
    cudaGetSymbolAddress((void**)&A, g_A);

    cudaFuncSetAttribute(gemm_tc,
                         cudaFuncAttributeMaxDynamicSharedMemorySize, G_SMEM);
    cudaFuncSetAttribute(flash_kernel,
                         cudaFuncAttributeMaxDynamicSharedMemorySize, FLASH_SMEM);

    // RoPE table (independent of projections)
    rope_table<<<(SEQ * 64 + 255) / 256, 256>>>();

    // projections (3xTF32 mma.sync)
    gemm_tc<<<dim3(DIM  /128, SEQ/128), 256, G_SMEM>>>(x, wq, Q, SEQ, DIM,   DIM);
    gemm_tc<<<dim3(KVDIM/128, SEQ/128), 256, G_SMEM>>>(x, wk, K, SEQ, KVDIM, DIM);
    gemm_tc<<<dim3(KVDIM/128, SEQ/128), 256, G_SMEM>>>(x, wv, V, SEQ, KVDIM, DIM);

    // RoPE apply (Q + K fused)
    rope_apply<<<(ROPE_TOTQ + ROPE_TOTK + 255) / 256, 256>>>(Q, K);

    // attention
    flash_kernel<<<dim3(SEQ/BQ, NH), 256, FLASH_SMEM>>>(Q, K, V, A);

    // output projection (3xTF32 mma.sync)
    gemm_tc<<<dim3(DIM/128, SEQ/128), 256, G_SMEM>>>(A, wo, out, SEQ, DIM, DIM);
}